// round 1
// baseline (speedup 1.0000x reference)
#include <cuda_runtime.h>
#include <math.h>

// ---------------------------------------------------------------------------
// PlaneElement: fused Green-Ampt infiltration + MUSCL kinematic wave + Manning
// Inputs (metadata order):
//  0 depth[N] f32, 1 rain_rate, 2 dt, 3 cum_rain(unused), 4 theta_current,
//  5 F_cumulative, 6 WID, 7 SS1, 8 SS2, 9 MAN, 10 SL, 11 dx, 12 Ks, 13 psi,
// 14 theta_s   (all scalars are 1-element f32 arrays)
// Output: 4 f32: [outflow_q, infil_rate_element, infil_depth_element, max_cfl]
// ---------------------------------------------------------------------------

#define BLOCK 256
#define TILE  2048
#define MAX_BLOCKS 8192
#define EPSF  1e-8f

struct Consts {
    float raindt;      // rain_rate * dt
    float Ka, Kb;      // fp*dt = Ka + Kb*depth
    float WID, rcpWID; // width, 1/width
    float css;         // sqrt(1+SS1^2)+sqrt(1+SS2^2)
    float cman;        // sqrt(SL)/MAN
    float dtdx;        // dt/dx
    float inv_dt;      // 1/dt
};

__device__ Consts g_c;
__device__ float  g_psum[MAX_BLOCKS];
__device__ float  g_pmax[MAX_BLOCKS];
__device__ float  g_outflow;

// ---------------------------------------------------------------------------
__global__ void setup_kernel(const float* rain_rate, const float* dt,
                             const float* theta_current, const float* F_cumulative,
                             const float* WID, const float* SS1, const float* SS2,
                             const float* MAN, const float* SL, const float* dx,
                             const float* Ks, const float* psi, const float* theta_s)
{
    float rr  = *rain_rate,  dtv = *dt,  th = *theta_current, F = *F_cumulative;
    float wid = *WID, ss1 = *SS1, ss2 = *SS2, man = *MAN, sl = *SL, dxv = *dx;
    float ks  = *Ks,  ps  = *psi, ths = *theta_s;

    Consts c;
    c.raindt = rr * dtv;
    float dtheta = fmaxf(ths - th, 0.0f);
    float F_safe = fmaxf(F, 1e-6f);
    float ksdt   = ks * dtv;
    c.Kb = ksdt / F_safe;                 // fp*dt = ksdt*(1 + (psi*dtheta + d)/F_safe)
    c.Ka = ksdt + c.Kb * (ps * dtheta);   //       = Ka + Kb*d
    c.WID = wid;
    c.rcpWID = 1.0f / wid;
    c.css  = sqrtf(1.0f + ss1 * ss1) + sqrtf(1.0f + ss2 * ss2);
    c.cman = sqrtf(sl) / man;
    c.dtdx = dtv / dxv;
    c.inv_dt = 1.0f / dtv;
    g_c = c;
}

// (A_safe/wp)^(2/3) — the shape factor of Manning's q; q = A * p * cman
__device__ __forceinline__ float manning_p(float A, const Consts& c)
{
    float h      = A * c.rcpWID;
    float wp     = fmaf(h, c.css, c.WID);
    float A_safe = fmaxf(A, EPSF);
    float r      = __fdividef(A_safe, wp);
    return __powf(r, 0.66666667f);
}

// ---------------------------------------------------------------------------
__global__ void __launch_bounds__(BLOCK)
main_kernel(const float* __restrict__ depth, int N)
{
    // sA[k]  = A at global index (base - 2 + k), k in [0, TILE+3)
    // sF[j]  = flux at global index (base - 1 + j), j in [0, TILE+1)
    __shared__ float sA[TILE + 3];
    __shared__ float sF[TILE + 1];
    __shared__ float wsum[BLOCK / 32];
    __shared__ float wmax[BLOCK / 32];

    const Consts c = g_c;
    const int base = blockIdx.x * TILE;
    const int tid  = threadIdx.x;

    // ---- phase 1: Green-Ampt + rain -> A, accumulate owned infiltration ----
    float local_sum = 0.0f;
    #pragma unroll 1
    for (int k = tid; k < TILE + 3; k += BLOCK) {
        int g = base - 2 + k;
        float Aval = 0.0f;
        if (g >= 0 && g < N) {
            float d     = depth[g];
            float fpdt  = fmaf(c.Kb, d, c.Ka);
            float avail = c.raindt + d;
            float infil = fminf(fpdt, avail);
            float surf  = fmaxf(avail - infil, 0.0f);
            Aval = surf * c.WID;
            if (g >= base && g < base + TILE)   // owned element
                local_sum += infil;
        }
        sA[k] = Aval;
    }
    __syncthreads();

    // ---- phase 2: MUSCL face state + Manning flux for [base-1, base+TILE) ----
    #pragma unroll 1
    for (int k = tid; k < TILE + 1; k += BLOCK) {
        int g   = base - 1 + k;
        float A = sA[k + 1];
        float slope = 0.0f;
        if (g > 0 && g < N - 1) {
            float d1 = A - sA[k];
            float d2 = sA[k + 2] - A;
            float m  = (fabsf(d1) < fabsf(d2)) ? d1 : d2;
            slope    = (d1 * d2 > 0.0f) ? m : 0.0f;
        }
        float Aface = fmaf(0.5f, slope, A);
        sF[k] = Aface * manning_p(Aface, c) * c.cman;
    }
    __syncthreads();

    // ---- phase 3: update, discharge, CFL ----
    float local_max = 0.0f;
    #pragma unroll 1
    for (int k = tid; k < TILE; k += BLOCK) {
        int g = base + k;
        if (g < N) {
            float A       = sA[k + 2];
            float flux    = sF[k + 1];
            float flux_in = (g == 0) ? 0.0f : sF[k];
            float A_next  = fmaxf(fmaf(-c.dtdx, flux - flux_in, A), 0.0f);
            float p       = manning_p(A_next, c);
            // vel = Q / max(A_next, EPS) with Q = A_next*p*cman
            //     = p*cman * min(A_next/EPS, 1)
            float vel = p * c.cman * fminf(A_next * 1e8f, 1.0f);
            local_max = fmaxf(local_max, vel);
            if (g == N - 1)
                g_outflow = A_next * p * c.cman;
        }
    }

    // ---- deterministic block reduction ----
    #pragma unroll
    for (int o = 16; o > 0; o >>= 1) {
        local_sum += __shfl_down_sync(0xffffffffu, local_sum, o);
        local_max  = fmaxf(local_max, __shfl_down_sync(0xffffffffu, local_max, o));
    }
    int warp = tid >> 5, lane = tid & 31;
    if (lane == 0) { wsum[warp] = local_sum; wmax[warp] = local_max; }
    __syncthreads();
    if (tid == 0) {
        float s = 0.0f, m = 0.0f;
        #pragma unroll
        for (int w = 0; w < BLOCK / 32; w++) {
            s += wsum[w];
            m = fmaxf(m, wmax[w]);
        }
        g_psum[blockIdx.x] = s;
        g_pmax[blockIdx.x] = m;
    }
}

// ---------------------------------------------------------------------------
__global__ void __launch_bounds__(1024)
finalize_kernel(float* __restrict__ out, int nblocks, float Nf)
{
    __shared__ float ssum[32];
    __shared__ float smax[32];
    int tid = threadIdx.x;

    float s = 0.0f, m = 0.0f;
    for (int i = tid; i < nblocks; i += 1024) {
        s += g_psum[i];
        m  = fmaxf(m, g_pmax[i]);
    }
    #pragma unroll
    for (int o = 16; o > 0; o >>= 1) {
        s += __shfl_down_sync(0xffffffffu, s, o);
        m  = fmaxf(m, __shfl_down_sync(0xffffffffu, m, o));
    }
    int warp = tid >> 5, lane = tid & 31;
    if (lane == 0) { ssum[warp] = s; smax[warp] = m; }
    __syncthreads();
    if (tid == 0) {
        float st = 0.0f, mt = 0.0f;
        #pragma unroll
        for (int w = 0; w < 32; w++) {
            st += ssum[w];
            mt  = fmaxf(mt, smax[w]);
        }
        const Consts c = g_c;
        float mean_depth = st / Nf;          // infil_depth_element
        out[0] = g_outflow;                  // outflow_q
        out[1] = mean_depth * c.inv_dt;      // infil_rate_element
        out[2] = mean_depth;                 // infil_depth_element
        out[3] = mt * c.dtdx;                // max_cfl = max(vel)*dt/dx
    }
}

// ---------------------------------------------------------------------------
extern "C" void kernel_launch(void* const* d_in, const int* in_sizes, int n_in,
                              void* d_out, int out_size)
{
    const float* depth = (const float*)d_in[0];
    const int N = in_sizes[0];
    int nblocks = (N + TILE - 1) / TILE;
    if (nblocks > MAX_BLOCKS) nblocks = MAX_BLOCKS;  // N=2^22 -> 2048 blocks

    setup_kernel<<<1, 1>>>(
        (const float*)d_in[1],  (const float*)d_in[2],  (const float*)d_in[4],
        (const float*)d_in[5],  (const float*)d_in[6],  (const float*)d_in[7],
        (const float*)d_in[8],  (const float*)d_in[9],  (const float*)d_in[10],
        (const float*)d_in[11], (const float*)d_in[12], (const float*)d_in[13],
        (const float*)d_in[14]);

    main_kernel<<<nblocks, BLOCK>>>(depth, N);

    finalize_kernel<<<1, 1024>>>((float*)d_out, nblocks, (float)N);
}

// round 2
// speedup vs baseline: 1.3053x; 1.3053x over previous
#include <cuda_runtime.h>
#include <math.h>

// ---------------------------------------------------------------------------
// PlaneElement fused: Green-Ampt infiltration + MUSCL kinematic wave + Manning
// Single-launch version: per-block consts, interior fast path, last-block
// finalize via atomic ticket (deterministic fixed-order reductions).
// Inputs (metadata order):
//  0 depth[N] f32, 1 rain_rate, 2 dt, 3 cum_rain(unused), 4 theta_current,
//  5 F_cumulative, 6 WID, 7 SS1, 8 SS2, 9 MAN, 10 SL, 11 dx, 12 Ks, 13 psi,
// 14 theta_s
// Output: 4 f32: [outflow_q, infil_rate_element, infil_depth_element, max_cfl]
// ---------------------------------------------------------------------------

#define BLOCK 256
#define TILE  2048
#define MAX_BLOCKS 8192
#define EPSF  1e-8f

struct Consts {
    float raindt;      // rain_rate * dt
    float Ka, Kb;      // fp*dt = Ka + Kb*depth
    float WID, rcpWID;
    float css;         // sqrt(1+SS1^2)+sqrt(1+SS2^2)
    float cman;        // sqrt(SL)/MAN
    float dtdx;        // dt/dx
    float inv_dt;
};

__device__ float        g_psum[MAX_BLOCKS];
__device__ float        g_pmax[MAX_BLOCKS];
__device__ float        g_outflow;
__device__ unsigned int g_count = 0;

// (A_safe/wp)^(2/3); manning q = A * p * cman
__device__ __forceinline__ float manning_p(float A, const Consts& c)
{
    float h      = A * c.rcpWID;
    float wp     = fmaf(h, c.css, c.WID);
    float A_safe = fmaxf(A, EPSF);
    float r      = __fdividef(A_safe, wp);
    return __powf(r, 0.66666667f);
}

__global__ void __launch_bounds__(BLOCK)
fused_kernel(const float* __restrict__ depth, int N, int nblocks,
             float* __restrict__ out,
             const float* rain_rate, const float* dt,
             const float* theta_current, const float* F_cumulative,
             const float* WID, const float* SS1, const float* SS2,
             const float* MAN, const float* SL, const float* dx,
             const float* Ks, const float* psi, const float* theta_s)
{
    // sA[k] = A at global index (base - 4 + k), k in [0, TILE+8): padded halo
    // for 16B-aligned float4 stores. Element g lives at sA[g - base + 4].
    __shared__ __align__(16) float sA[TILE + 8];
    __shared__ float sF[TILE + 1];     // sF[j] = flux at node (base - 1 + j)
    __shared__ Consts sc;
    __shared__ float wsum[BLOCK / 32];
    __shared__ float wmax[BLOCK / 32];
    __shared__ int   s_last;

    const int tid  = threadIdx.x;
    const int base = blockIdx.x * TILE;

    if (tid == 0) {
        float rr  = *rain_rate,  dtv = *dt,  th = *theta_current, F = *F_cumulative;
        float wid = *WID, ss1 = *SS1, ss2 = *SS2, man = *MAN, sl = *SL, dxv = *dx;
        float ks  = *Ks,  ps  = *psi, ths = *theta_s;
        Consts c;
        c.raindt = rr * dtv;
        float dtheta = fmaxf(ths - th, 0.0f);
        float F_safe = fmaxf(F, 1e-6f);
        float ksdt   = ks * dtv;
        c.Kb = ksdt / F_safe;
        c.Ka = ksdt + c.Kb * (ps * dtheta);
        c.WID = wid;
        c.rcpWID = 1.0f / wid;
        c.css  = sqrtf(1.0f + ss1 * ss1) + sqrtf(1.0f + ss2 * ss2);
        c.cman = sqrtf(sl) / man;
        c.dtdx = dtv / dxv;
        c.inv_dt = 1.0f / dtv;
        sc = c;
    }
    __syncthreads();
    const Consts c = sc;

    const bool interior = (base - 4 >= 0) && (base + TILE + 4 <= N);

    float local_sum = 0.0f;
    float local_max = 0.0f;

    if (interior) {
        // ---- phase 1: Green-Ampt + rain -> A (vectorized, no bounds) ----
        const float4* dp = (const float4*)(depth + base);
        float4* sA4 = (float4*)(sA + 4);
        #pragma unroll
        for (int it = 0; it < TILE / (4 * BLOCK); it++) {
            int idx = it * BLOCK + tid;
            float4 d4 = __ldg(dp + idx);
            float4 a4;
            {
                float fpdt  = fmaf(c.Kb, d4.x, c.Ka);
                float avail = c.raindt + d4.x;
                float infil = fminf(fpdt, avail);
                local_sum  += infil;
                a4.x = fmaxf(avail - infil, 0.0f) * c.WID;
            }
            {
                float fpdt  = fmaf(c.Kb, d4.y, c.Ka);
                float avail = c.raindt + d4.y;
                float infil = fminf(fpdt, avail);
                local_sum  += infil;
                a4.y = fmaxf(avail - infil, 0.0f) * c.WID;
            }
            {
                float fpdt  = fmaf(c.Kb, d4.z, c.Ka);
                float avail = c.raindt + d4.z;
                float infil = fminf(fpdt, avail);
                local_sum  += infil;
                a4.z = fmaxf(avail - infil, 0.0f) * c.WID;
            }
            {
                float fpdt  = fmaf(c.Kb, d4.w, c.Ka);
                float avail = c.raindt + d4.w;
                float infil = fminf(fpdt, avail);
                local_sum  += infil;
                a4.w = fmaxf(avail - infil, 0.0f) * c.WID;
            }
            sA4[idx] = a4;
        }
        // halo: g in {base-2, base-1, base+TILE, base+TILE+1}
        if (tid < 4) {
            int g = (tid < 2) ? (base - 2 + tid) : (base + TILE + tid - 2);
            int k = g - base + 4;
            float d     = depth[g];
            float fpdt  = fmaf(c.Kb, d, c.Ka);
            float avail = c.raindt + d;
            float infil = fminf(fpdt, avail);
            sA[k] = fmaxf(avail - infil, 0.0f) * c.WID;
        }
        __syncthreads();

        // ---- phase 2: MUSCL face + Manning flux, faces [base-1, base+TILE) ----
        #pragma unroll 1
        for (int j = tid; j <= TILE; j += BLOCK) {
            float A  = sA[j + 3];
            float d1 = A - sA[j + 2];
            float d2 = sA[j + 4] - A;
            float m  = (fabsf(d1) < fabsf(d2)) ? d1 : d2;
            float slope = (d1 * d2 > 0.0f) ? m : 0.0f;
            float Aface = fmaf(0.5f, slope, A);
            sF[j] = Aface * manning_p(Aface, c) * c.cman;
        }
        __syncthreads();

        // ---- phase 3: update + CFL ----
        #pragma unroll 1
        for (int k = tid; k < TILE; k += BLOCK) {
            float A      = sA[k + 4];
            float dflux  = sF[k + 1] - sF[k];
            float A_next = fmaxf(fmaf(-c.dtdx, dflux, A), 0.0f);
            float p      = manning_p(A_next, c);
            float vel    = p * c.cman * fminf(A_next * 1e8f, 1.0f);
            local_max    = fmaxf(local_max, vel);
        }
    } else {
        // ---- edge blocks: fully guarded scalar path ----
        #pragma unroll 1
        for (int k = tid; k < TILE + 8; k += BLOCK) {
            int g = base - 4 + k;
            float Aval = 0.0f;
            if (g >= 0 && g < N) {
                float d     = depth[g];
                float fpdt  = fmaf(c.Kb, d, c.Ka);
                float avail = c.raindt + d;
                float infil = fminf(fpdt, avail);
                Aval = fmaxf(avail - infil, 0.0f) * c.WID;
                if (g >= base && g < base + TILE)
                    local_sum += infil;
            }
            sA[k] = Aval;
        }
        __syncthreads();

        #pragma unroll 1
        for (int j = tid; j <= TILE; j += BLOCK) {
            int g   = base - 1 + j;
            float A = sA[j + 3];
            float slope = 0.0f;
            if (g > 0 && g < N - 1) {
                float d1 = A - sA[j + 2];
                float d2 = sA[j + 4] - A;
                float m  = (fabsf(d1) < fabsf(d2)) ? d1 : d2;
                slope    = (d1 * d2 > 0.0f) ? m : 0.0f;
            }
            float Aface = fmaf(0.5f, slope, A);
            sF[j] = Aface * manning_p(Aface, c) * c.cman;
        }
        __syncthreads();

        #pragma unroll 1
        for (int k = tid; k < TILE; k += BLOCK) {
            int g = base + k;
            if (g < N) {
                float A       = sA[k + 4];
                float flux    = sF[k + 1];
                float flux_in = (g == 0) ? 0.0f : sF[k];
                float A_next  = fmaxf(fmaf(-c.dtdx, flux - flux_in, A), 0.0f);
                float p       = manning_p(A_next, c);
                float vel     = p * c.cman * fminf(A_next * 1e8f, 1.0f);
                local_max     = fmaxf(local_max, vel);
                if (g == N - 1)
                    g_outflow = A_next * p * c.cman;
            }
        }
    }

    // ---- deterministic block reduction ----
    #pragma unroll
    for (int o = 16; o > 0; o >>= 1) {
        local_sum += __shfl_down_sync(0xffffffffu, local_sum, o);
        local_max  = fmaxf(local_max, __shfl_down_sync(0xffffffffu, local_max, o));
    }
    int warp = tid >> 5, lane = tid & 31;
    if (lane == 0) { wsum[warp] = local_sum; wmax[warp] = local_max; }
    __syncthreads();
    if (tid == 0) {
        float s = 0.0f, m = 0.0f;
        #pragma unroll
        for (int w = 0; w < BLOCK / 32; w++) {
            s += wsum[w];
            m = fmaxf(m, wmax[w]);
        }
        g_psum[blockIdx.x] = s;
        g_pmax[blockIdx.x] = m;
        __threadfence();
        unsigned int ticket = atomicAdd(&g_count, 1u);
        s_last = (ticket == (unsigned int)(nblocks - 1)) ? 1 : 0;
    }
    __syncthreads();

    // ---- last-to-finish block: fixed-order grid reduction + outputs ----
    if (s_last) {
        __threadfence();  // acquire all blocks' partials
        float s = 0.0f, m = 0.0f;
        for (int i = tid; i < nblocks; i += BLOCK) {
            s += g_psum[i];
            m  = fmaxf(m, g_pmax[i]);
        }
        #pragma unroll
        for (int o = 16; o > 0; o >>= 1) {
            s += __shfl_down_sync(0xffffffffu, s, o);
            m  = fmaxf(m, __shfl_down_sync(0xffffffffu, m, o));
        }
        if (lane == 0) { wsum[warp] = s; wmax[warp] = m; }
        __syncthreads();
        if (tid == 0) {
            float st = 0.0f, mt = 0.0f;
            #pragma unroll
            for (int w = 0; w < BLOCK / 32; w++) {
                st += wsum[w];
                mt  = fmaxf(mt, wmax[w]);
            }
            float mean_depth = st / (float)N;
            out[0] = g_outflow;              // outflow_q
            out[1] = mean_depth * c.inv_dt;  // infil_rate_element
            out[2] = mean_depth;             // infil_depth_element
            out[3] = mt * c.dtdx;            // max_cfl
            g_count = 0;                     // reset for next graph replay
        }
    }
}

// ---------------------------------------------------------------------------
extern "C" void kernel_launch(void* const* d_in, const int* in_sizes, int n_in,
                              void* d_out, int out_size)
{
    const float* depth = (const float*)d_in[0];
    const int N = in_sizes[0];
    int nblocks = (N + TILE - 1) / TILE;
    if (nblocks > MAX_BLOCKS) nblocks = MAX_BLOCKS;  // N=2^22 -> 2048 blocks

    fused_kernel<<<nblocks, BLOCK>>>(
        depth, N, nblocks, (float*)d_out,
        (const float*)d_in[1],  (const float*)d_in[2],  (const float*)d_in[4],
        (const float*)d_in[5],  (const float*)d_in[6],  (const float*)d_in[7],
        (const float*)d_in[8],  (const float*)d_in[9],  (const float*)d_in[10],
        (const float*)d_in[11], (const float*)d_in[12], (const float*)d_in[13],
        (const float*)d_in[14]);
}

// round 3
// speedup vs baseline: 1.4443x; 1.1064x over previous
#include <cuda_runtime.h>
#include <math.h>

// ---------------------------------------------------------------------------
// PlaneElement fused, register-resident stencil version.
// Each interior thread owns 8 consecutive elements entirely in registers:
// depth[11] -> A[11] -> flux[9] -> A_next[8], no shared memory, no syncs.
// Edge blocks (2) use the guarded smem path. Grid finale via atomic ticket.
// Output: [outflow_q, infil_rate_element, infil_depth_element, max_cfl]
// ---------------------------------------------------------------------------

#define BLOCK 256
#define EPT   8                  // elements per thread
#define TILE  (BLOCK * EPT)      // 2048
#define MAX_BLOCKS 8192
#define EPSF  1e-8f

struct Consts {
    float raindt;      // rain_rate * dt
    float Ka, Kb;      // fp*dt = Ka + Kb*depth
    float WID, rcpWID;
    float css;         // sqrt(1+SS1^2)+sqrt(1+SS2^2)
    float cman;        // sqrt(SL)/MAN
    float dtdx;        // dt/dx
    float inv_dt;
};

__device__ float        g_psum[MAX_BLOCKS];
__device__ float        g_pmax[MAX_BLOCKS];
__device__ float        g_outflow;
__device__ unsigned int g_count = 0;

// (max(A,EPS)/wp)^(2/3); manning q = A * p * cman
__device__ __forceinline__ float manning_p(float A, const Consts& c)
{
    float h      = A * c.rcpWID;
    float wp     = fmaf(h, c.css, c.WID);
    float A_safe = fmaxf(A, EPSF);
    float r      = __fdividef(A_safe, wp);
    return __powf(r, 0.66666667f);
}

// Green-Ampt + rain: returns A, writes infil (depth infiltrated this step)
__device__ __forceinline__ float ga_A(float d, const Consts& c, float& infil)
{
    float fpdt  = fmaf(c.Kb, d, c.Ka);
    float avail = c.raindt + d;
    infil       = fminf(fpdt, avail);
    return fmaxf(avail - infil, 0.0f) * c.WID;
}

__global__ void __launch_bounds__(BLOCK)
fused_kernel(const float* __restrict__ depth, int N, int nblocks,
             float* __restrict__ out,
             const float* rain_rate, const float* dt,
             const float* theta_current, const float* F_cumulative,
             const float* WID, const float* SS1, const float* SS2,
             const float* MAN, const float* SL, const float* dx,
             const float* Ks, const float* psi, const float* theta_s)
{
    __shared__ float sA[TILE + 8];   // edge path only
    __shared__ float sF[TILE + 1];   // edge path only
    __shared__ Consts sc;
    __shared__ float wsum[BLOCK / 32];
    __shared__ float wmax[BLOCK / 32];
    __shared__ int   s_last;

    const int tid  = threadIdx.x;
    const int base = blockIdx.x * TILE;

    if (tid == 0) {
        float rr  = *rain_rate,  dtv = *dt,  th = *theta_current, F = *F_cumulative;
        float wid = *WID, ss1 = *SS1, ss2 = *SS2, man = *MAN, sl = *SL, dxv = *dx;
        float ks  = *Ks,  ps  = *psi, ths = *theta_s;
        Consts c;
        c.raindt = rr * dtv;
        float dtheta = fmaxf(ths - th, 0.0f);
        float F_safe = fmaxf(F, 1e-6f);
        float ksdt   = ks * dtv;
        c.Kb = ksdt / F_safe;
        c.Ka = ksdt + c.Kb * (ps * dtheta);
        c.WID = wid;
        c.rcpWID = 1.0f / wid;
        c.css  = sqrtf(1.0f + ss1 * ss1) + sqrtf(1.0f + ss2 * ss2);
        c.cman = sqrtf(sl) / man;
        c.dtdx = dtv / dxv;
        c.inv_dt = 1.0f / dtv;
        sc = c;
    }
    __syncthreads();
    const Consts c = sc;

    const bool interior = (base - 2 >= 0) && (base + TILE + 8 <= N);

    float local_sum = 0.0f;
    float local_max = 0.0f;

    if (interior) {
        // ------------------ register-resident path ------------------
        const int t0 = base + tid * EPT;

        // d[k] = depth[t0 - 2 + k], k in [0, 11)
        float d[EPT + 3];
        {
            float4 q0 = *(const float4*)(depth + t0);
            float4 q1 = *(const float4*)(depth + t0 + 4);
            d[2] = q0.x; d[3] = q0.y; d[4] = q0.z; d[5] = q0.w;
            d[6] = q1.x; d[7] = q1.y; d[8] = q1.z; d[9] = q1.w;
            d[0]  = __ldg(depth + t0 - 2);
            d[1]  = __ldg(depth + t0 - 1);
            d[10] = __ldg(depth + t0 + EPT);
        }

        // A[k] for same indices; accumulate infil over owned (k=2..9)
        float A[EPT + 3];
        #pragma unroll
        for (int k = 0; k < EPT + 3; k++) {
            float infil;
            A[k] = ga_A(d[k], c, infil);
            if (k >= 2 && k < 2 + EPT) local_sum += infil;
        }

        // flux[i] = outgoing Manning flux of node (t0 - 1 + i), i in [0, 9)
        // slope(node) = minmod(A - A_left, A_right - A)
        float flux[EPT + 1];
        #pragma unroll
        for (int i = 0; i < EPT + 1; i++) {
            float a = A[i + 1] - A[i];
            float b = A[i + 2] - A[i + 1];
            float m = (fabsf(a) < fabsf(b)) ? a : b;
            float slope = (a * b > 0.0f) ? m : 0.0f;
            float Aface = fmaf(0.5f, slope, A[i + 1]);
            flux[i] = Aface * manning_p(Aface, c) * c.cman;
        }

        // update + CFL for owned elements
        #pragma unroll
        for (int k = 0; k < EPT; k++) {
            float dflux  = flux[k + 1] - flux[k];
            float A_next = fmaxf(fmaf(-c.dtdx, dflux, A[k + 2]), 0.0f);
            float p      = manning_p(A_next, c);
            float vel    = p * c.cman * fminf(A_next * 1e8f, 1.0f);
            local_max    = fmaxf(local_max, vel);
        }
    } else {
        // ------------------ guarded smem path (2 blocks) ------------------
        #pragma unroll 1
        for (int k = tid; k < TILE + 8; k += BLOCK) {
            int g = base - 4 + k;
            float Aval = 0.0f;
            if (g >= 0 && g < N) {
                float infil;
                Aval = ga_A(depth[g], c, infil);
                if (g >= base && g < base + TILE)
                    local_sum += infil;
            }
            sA[k] = Aval;
        }
        __syncthreads();

        #pragma unroll 1
        for (int j = tid; j <= TILE; j += BLOCK) {
            int g   = base - 1 + j;
            float A = sA[j + 3];
            float slope = 0.0f;
            if (g > 0 && g < N - 1) {
                float d1 = A - sA[j + 2];
                float d2 = sA[j + 4] - A;
                float m  = (fabsf(d1) < fabsf(d2)) ? d1 : d2;
                slope    = (d1 * d2 > 0.0f) ? m : 0.0f;
            }
            float Aface = fmaf(0.5f, slope, A);
            sF[j] = Aface * manning_p(Aface, c) * c.cman;
        }
        __syncthreads();

        #pragma unroll 1
        for (int k = tid; k < TILE; k += BLOCK) {
            int g = base + k;
            if (g < N) {
                float A       = sA[k + 4];
                float flux    = sF[k + 1];
                float flux_in = (g == 0) ? 0.0f : sF[k];
                float A_next  = fmaxf(fmaf(-c.dtdx, flux - flux_in, A), 0.0f);
                float p       = manning_p(A_next, c);
                float vel     = p * c.cman * fminf(A_next * 1e8f, 1.0f);
                local_max     = fmaxf(local_max, vel);
                if (g == N - 1)
                    g_outflow = A_next * p * c.cman;
            }
        }
    }

    // ---- deterministic block reduction ----
    #pragma unroll
    for (int o = 16; o > 0; o >>= 1) {
        local_sum += __shfl_down_sync(0xffffffffu, local_sum, o);
        local_max  = fmaxf(local_max, __shfl_down_sync(0xffffffffu, local_max, o));
    }
    int warp = tid >> 5, lane = tid & 31;
    if (lane == 0) { wsum[warp] = local_sum; wmax[warp] = local_max; }
    __syncthreads();
    if (tid == 0) {
        float s = 0.0f, m = 0.0f;
        #pragma unroll
        for (int w = 0; w < BLOCK / 32; w++) {
            s += wsum[w];
            m = fmaxf(m, wmax[w]);
        }
        g_psum[blockIdx.x] = s;
        g_pmax[blockIdx.x] = m;
        __threadfence();
        unsigned int ticket = atomicAdd(&g_count, 1u);
        s_last = (ticket == (unsigned int)(nblocks - 1)) ? 1 : 0;
    }
    __syncthreads();

    // ---- last-to-finish block: fixed-order grid reduction + outputs ----
    if (s_last) {
        __threadfence();
        float s = 0.0f, m = 0.0f;
        for (int i = tid; i < nblocks; i += BLOCK) {
            s += g_psum[i];
            m  = fmaxf(m, g_pmax[i]);
        }
        #pragma unroll
        for (int o = 16; o > 0; o >>= 1) {
            s += __shfl_down_sync(0xffffffffu, s, o);
            m  = fmaxf(m, __shfl_down_sync(0xffffffffu, m, o));
        }
        if (lane == 0) { wsum[warp] = s; wmax[warp] = m; }
        __syncthreads();
        if (tid == 0) {
            float st = 0.0f, mt = 0.0f;
            #pragma unroll
            for (int w = 0; w < BLOCK / 32; w++) {
                st += wsum[w];
                mt  = fmaxf(mt, wmax[w]);
            }
            float mean_depth = st / (float)N;
            out[0] = g_outflow;
            out[1] = mean_depth * c.inv_dt;
            out[2] = mean_depth;
            out[3] = mt * c.dtdx;
            g_count = 0;   // reset for next graph replay
        }
    }
}

// ---------------------------------------------------------------------------
extern "C" void kernel_launch(void* const* d_in, const int* in_sizes, int n_in,
                              void* d_out, int out_size)
{
    const float* depth = (const float*)d_in[0];
    const int N = in_sizes[0];
    int nblocks = (N + TILE - 1) / TILE;
    if (nblocks > MAX_BLOCKS) nblocks = MAX_BLOCKS;  // N=2^22 -> 2048 blocks

    fused_kernel<<<nblocks, BLOCK>>>(
        depth, N, nblocks, (float*)d_out,
        (const float*)d_in[1],  (const float*)d_in[2],  (const float*)d_in[4],
        (const float*)d_in[5],  (const float*)d_in[6],  (const float*)d_in[7],
        (const float*)d_in[8],  (const float*)d_in[9],  (const float*)d_in[10],
        (const float*)d_in[11], (const float*)d_in[12], (const float*)d_in[13],
        (const float*)d_in[14]);
}